// round 1
// baseline (speedup 1.0000x reference)
#include <cuda_runtime.h>
#include <cuda_bf16.h>
#include <math.h>

// Problem constants
#define B      256
#define NNEG   1000
#define H      3
#define D      128
#define NC0    25000
#define NC1    2500
#define NC2    250
#define CMAX   250          // neg indices < min(NUM_CLUSTER) = 250
#define CPAD   256          // padded cluster dim
#define EPSF   1e-6f

// Intermediates (device globals: no allocation allowed)
__device__ float g_SE[B * H * D];          // normalized semantic embs [b][h][d]
__device__ float g_CNT[H * D * CPAD];      // normalized centroids, transposed [h][d][c] (c>=250 stays 0)
__device__ float g_S[B * H * CPAD];        // sim matrix (dot+1)/2, [b][h][c]
__device__ float g_loss[B];                // per-sample (pos+neg)/2

// ---------------------------------------------------------------------------
// K1: normalize semantic embeddings (768 rows) and first-250 centroid rows
//     per hierarchy (750 rows). One warp per row of 128 floats.
// ---------------------------------------------------------------------------
__global__ void k_normalize(const float* __restrict__ se,
                            const float* __restrict__ c0,
                            const float* __restrict__ c1,
                            const float* __restrict__ c2) {
    int r    = blockIdx.x * 8 + (threadIdx.x >> 5);
    int lane = threadIdx.x & 31;
    const int NROWS = B * H + H * CMAX;    // 768 + 750
    if (r >= NROWS) return;

    const float* src;
    if (r < B * H) {
        src = se + r * D;                  // [b][h][d] contiguous
    } else {
        int rc = r - B * H;
        int h = rc / CMAX, c = rc % CMAX;
        const float* cents = (h == 0) ? c0 : (h == 1) ? c1 : c2;
        src = cents + (long)c * D;
    }
    float4 v = ((const float4*)src)[lane];
    float s = v.x * v.x + v.y * v.y + v.z * v.z + v.w * v.w;
    #pragma unroll
    for (int o = 16; o > 0; o >>= 1) s += __shfl_xor_sync(0xffffffffu, s, o);
    float inv = 1.0f / fmaxf(sqrtf(s), 1e-12f);
    v.x *= inv; v.y *= inv; v.z *= inv; v.w *= inv;

    if (r < B * H) {
        ((float4*)(g_SE + r * D))[lane] = v;
    } else {
        int rc = r - B * H;
        int h = rc / CMAX, c = rc % CMAX;
        int d = lane * 4;
        float* base = g_CNT + (h * D) * CPAD + c;  // transposed store [h][d][c]
        base[(d + 0) * CPAD] = v.x;
        base[(d + 1) * CPAD] = v.y;
        base[(d + 2) * CPAD] = v.z;
        base[(d + 3) * CPAD] = v.w;
    }
}

// ---------------------------------------------------------------------------
// K2: S[b][h][c] = (dot(SE[b,h], CN[h,c]) + 1) * 0.5 for c < 256 (padded).
//     grid = (8 c-tiles of 32, 32 b-tiles of 8, 3 h), block = 256 threads.
//     cn tile kept d-major in smem -> conflict-free LDS; se via broadcast LDS.
// ---------------------------------------------------------------------------
__global__ void k_sim() {
    __shared__ float cn_s[D * 32];    // [d][ci]
    __shared__ float se_s[8 * D];     // [bi][d]
    int h  = blockIdx.z;
    int c0 = blockIdx.x * 32;
    int b0 = blockIdx.y * 8;
    int tid = threadIdx.x;

    for (int i = tid; i < D * 32; i += 256) {
        int d = i >> 5, c = i & 31;
        cn_s[i] = g_CNT[(h * D + d) * CPAD + c0 + c];
    }
    for (int i = tid; i < 8 * D; i += 256) {
        int bb = i >> 7, d = i & 127;
        se_s[i] = g_SE[((b0 + bb) * H + h) * D + d];
    }
    __syncthreads();

    int ci = tid & 31, bi = tid >> 5;
    float acc = 0.0f;
    #pragma unroll
    for (int d = 0; d < D; d++)
        acc = fmaf(cn_s[d * 32 + ci], se_s[bi * D + d], acc);
    g_S[((b0 + bi) * H + h) * CPAD + c0 + ci] = (acc + 1.0f) * 0.5f;
}

// ---------------------------------------------------------------------------
// K3: per-sample loss. One block per b (256 threads).
//     pos path gathered/normalized on the fly (indices can span full tables);
//     negatives are pure lookups into the smem-resident S row.
// ---------------------------------------------------------------------------
__global__ void k_loss(const float* __restrict__ c0,
                       const float* __restrict__ c1,
                       const float* __restrict__ c2,
                       const int* __restrict__ i2c0,
                       const int* __restrict__ i2c1,
                       const int* __restrict__ i2c2,
                       const int* __restrict__ index,
                       const int* __restrict__ neg) {
    __shared__ float sS[H * CPAD];
    __shared__ float sPos[H];
    __shared__ int   sLab[H];
    __shared__ float redL[256];
    __shared__ float redC[256];

    int b = blockIdx.x, tid = threadIdx.x;
    for (int i = tid; i < H * CPAD; i += 256) sS[i] = g_S[b * H * CPAD + i];

    int w = tid >> 5, lane = tid & 31;
    if (w < H) {
        int idx = index[b];
        const int*   i2c   = (w == 0) ? i2c0 : (w == 1) ? i2c1 : i2c2;
        const float* cents = (w == 0) ? c0   : (w == 1) ? c1   : c2;
        int lab = i2c[idx];
        float4 cv = ((const float4*)(cents + (long)lab * D))[lane];
        float4 sv = ((const float4*)(g_SE + (b * H + w) * D))[lane];
        float ss = cv.x * cv.x + cv.y * cv.y + cv.z * cv.z + cv.w * cv.w;
        float dd = cv.x * sv.x + cv.y * sv.y + cv.z * sv.z + cv.w * sv.w;
        #pragma unroll
        for (int o = 16; o > 0; o >>= 1) {
            ss += __shfl_xor_sync(0xffffffffu, ss, o);
            dd += __shfl_xor_sync(0xffffffffu, dd, o);
        }
        if (lane == 0) {
            sPos[w] = (dd / fmaxf(sqrtf(ss), 1e-12f) + 1.0f) * 0.5f;
            sLab[w] = lab;
        }
    }
    __syncthreads();

    int lab0 = sLab[0], lab1 = sLab[1], lab2 = sLab[2];
    float sumL = 0.0f, cnt = 0.0f;
    for (int n = tid; n < NNEG; n += 256) {
        const int* p = neg + ((long)b * NNEG + n) * H;
        int i0 = p[0], i1 = p[1], i2 = p[2];
        float prod = sS[i0] * sS[CPAD + i1] * sS[2 * CPAD + i2];
        bool tn = (i0 != lab0) || (i1 != lab1) || (i2 != lab2);
        if (tn) {
            sumL += -__logf(1.0f - prod + EPSF);
            cnt  += 1.0f;
        }
    }
    redL[tid] = sumL; redC[tid] = cnt;
    __syncthreads();
    #pragma unroll
    for (int s = 128; s > 0; s >>= 1) {
        if (tid < s) { redL[tid] += redL[tid + s]; redC[tid] += redC[tid + s]; }
        __syncthreads();
    }
    if (tid == 0) {
        float posl = -__logf(sPos[0] * sPos[1] * sPos[2] + EPSF);
        float negl = redL[0] / (redC[0] + EPSF);
        g_loss[b] = 0.5f * (posl + negl);
    }
}

// ---------------------------------------------------------------------------
// K4: final deterministic reduction of 256 per-sample losses -> scalar mean.
// ---------------------------------------------------------------------------
__global__ void k_final(float* __restrict__ out) {
    __shared__ float red[256];
    int tid = threadIdx.x;
    red[tid] = g_loss[tid];
    __syncthreads();
    #pragma unroll
    for (int s = 128; s > 0; s >>= 1) {
        if (tid < s) red[tid] += red[tid + s];
        __syncthreads();
    }
    if (tid == 0) out[0] = red[0] * (1.0f / (float)B);
}

// ---------------------------------------------------------------------------
extern "C" void kernel_launch(void* const* d_in, const int* in_sizes, int n_in,
                              void* d_out, int out_size) {
    const float* se  = (const float*)d_in[0];
    const float* c0  = (const float*)d_in[1];
    const float* c1  = (const float*)d_in[2];
    const float* c2  = (const float*)d_in[3];
    const int* i2c0  = (const int*)d_in[4];
    const int* i2c1  = (const int*)d_in[5];
    const int* i2c2  = (const int*)d_in[6];
    const int* index = (const int*)d_in[7];
    const int* neg   = (const int*)d_in[8];
    float* out = (float*)d_out;

    const int nrows = B * H + H * CMAX;               // 1518
    k_normalize<<<(nrows + 7) / 8, 256>>>(se, c0, c1, c2);
    k_sim<<<dim3(CPAD / 32, B / 8, H), 256>>>();
    k_loss<<<B, 256>>>(c0, c1, c2, i2c0, i2c1, i2c2, index, neg);
    k_final<<<1, 256>>>(out);
}